// round 10
// baseline (speedup 1.0000x reference)
#include <cuda_runtime.h>
#include <cstdint>

// InvertAffine: (B, 3, 4) fp32 affine shift matrices.
// inverse top-3-rows = [R, -R t], R = (I3+A)^-1 via closed-form 3x3 adjugate.
//
// Round-10 hybrid: TMA bulk LOAD (R9's win: async 24 KB gmem->smem, zero
// per-thread L1tex read wavefronts, mbarrier complete_tx) + per-thread
// coalesced STG.128 STORE from smem (R8's win: stores drain asynchronously,
// block exits with writes in flight — removes R9's serialized
// wait_group/bulk-store epilogue that held 8 warps per block).

constexpr int TILE = 512;        // matrices per block
constexpr int TF4  = TILE * 3;   // 1536 float4 = 24 KB per buffer
constexpr unsigned TILE_BYTES = TF4 * 16;  // 24576

__device__ __forceinline__ void invert3(const float4 a0, const float4 a1, const float4 a2,
                                        float4& q0, float4& q1, float4& q2)
{
    // M = I3 + A, t = last column
    const float m00 = a0.x + 1.0f, m01 = a0.y,        m02 = a0.z,        t0 = a0.w;
    const float m10 = a1.x,        m11 = a1.y + 1.0f, m12 = a1.z,        t1 = a1.w;
    const float m20 = a2.x,        m21 = a2.y,        m22 = a2.z + 1.0f, t2 = a2.w;

    const float c00 = m11 * m22 - m12 * m21;
    const float c10 = m12 * m20 - m10 * m22;
    const float c20 = m10 * m21 - m11 * m20;
    const float det = m00 * c00 + m01 * c10 + m02 * c20;
    const float rdet = 1.0f / det;

    const float i00 = c00 * rdet;
    const float i01 = (m02 * m21 - m01 * m22) * rdet;
    const float i02 = (m01 * m12 - m02 * m11) * rdet;
    const float i10 = c10 * rdet;
    const float i11 = (m00 * m22 - m02 * m20) * rdet;
    const float i12 = (m02 * m10 - m00 * m12) * rdet;
    const float i20 = c20 * rdet;
    const float i21 = (m01 * m20 - m00 * m21) * rdet;
    const float i22 = (m00 * m11 - m01 * m10) * rdet;

    const float o0 = -(i00 * t0 + i01 * t1 + i02 * t2);
    const float o1 = -(i10 * t0 + i11 * t1 + i12 * t2);
    const float o2 = -(i20 * t0 + i21 * t1 + i22 * t2);

    q0 = make_float4(i00, i01, i02, o0);
    q1 = make_float4(i10, i11, i12, o1);
    q2 = make_float4(i20, i21, i22, o2);
}

// Fast path: full tiles. TMA bulk load in, STG.128 out.
__global__ void __launch_bounds__(256) invert_affine_hybrid_kernel(
    const float4* __restrict__ in, float4* __restrict__ out)
{
    __shared__ float4 s_in[TF4];    // 24 KB
    __shared__ float4 s_out[TF4];   // 24 KB
    __shared__ __align__(8) uint64_t mbar;

    const int t = threadIdx.x;
    const long long fbase = (long long)blockIdx.x * TF4;

    const uint32_t mbar_a = (uint32_t)__cvta_generic_to_shared(&mbar);
    const uint32_t s_in_a = (uint32_t)__cvta_generic_to_shared(s_in);

    if (t == 0) {
        asm volatile("mbarrier.init.shared.b64 [%0], 1;" :: "r"(mbar_a) : "memory");
        // init is visible to the async proxy before the TMA targets it —
        // same-thread issue order + fence below covers the proxy crossing.
        asm volatile("fence.proxy.async.shared::cta;" ::: "memory");
        asm volatile("mbarrier.arrive.expect_tx.shared.b64 _, [%0], %1;"
                     :: "r"(mbar_a), "r"(TILE_BYTES) : "memory");
        asm volatile(
            "cp.async.bulk.shared::cta.global.mbarrier::complete_tx::bytes "
            "[%0], [%1], %2, [%3];"
            :: "r"(s_in_a), "l"(in + fbase), "r"(TILE_BYTES), "r"(mbar_a)
            : "memory");
    }
    __syncthreads();  // all threads see the initialized barrier before waiting

    // All threads wait for the bulk load (phase parity 0)
    {
        uint32_t done;
        asm volatile(
            "{\n\t.reg .pred p;\n\t"
            "mbarrier.try_wait.parity.acquire.cta.shared::cta.b64 p, [%1], 0;\n\t"
            "selp.b32 %0, 1, 0, p;\n\t}"
            : "=r"(done) : "r"(mbar_a) : "memory");
        if (!done) {
            asm volatile(
                "{\n\t.reg .pred P1;\n\t"
                "WL_%=:\n\t"
                "mbarrier.try_wait.parity.acquire.cta.shared::cta.b64 P1, [%0], 0, 0x989680;\n\t"
                "@P1 bra.uni WD_%=;\n\t"
                "bra.uni WL_%=;\n\t"
                "WD_%=:\n\t}"
                :: "r"(mbar_a) : "memory");
        }
    }

#pragma unroll
    for (int m = 0; m < 2; m++) {
        const int mi = t + m * 256;
        float4 q0, q1, q2;
        invert3(s_in[3 * mi + 0], s_in[3 * mi + 1], s_in[3 * mi + 2], q0, q1, q2);
        s_out[3 * mi + 0] = q0;
        s_out[3 * mi + 1] = q1;
        s_out[3 * mi + 2] = q2;
    }
    __syncthreads();

    // Coalesced per-thread stores; block exits with writes in flight.
#pragma unroll
    for (int k = 0; k < 6; k++)
        out[fbase + t + k * 256] = s_out[t + k * 256];
}

// Tail: partial final tile (unused when B % 512 == 0), plain guarded path.
__global__ void __launch_bounds__(256) invert_affine_tail_kernel(
    const float4* __restrict__ in, float4* __restrict__ out, int mbase, int b)
{
    __shared__ float4 s_in[TF4];
    __shared__ float4 s_out[TF4];

    const int t = threadIdx.x;
    const long long fbase = (long long)mbase * 3;
    const int nmat = b - mbase;
    const int nf4 = nmat * 3;

#pragma unroll
    for (int k = 0; k < 6; k++) {
        const int idx = t + k * 256;
        if (idx < nf4) s_in[idx] = in[fbase + idx];
    }
    __syncthreads();

#pragma unroll
    for (int m = 0; m < 2; m++) {
        const int mi = t + m * 256;
        if (mi < nmat) {
            float4 q0, q1, q2;
            invert3(s_in[3 * mi + 0], s_in[3 * mi + 1], s_in[3 * mi + 2], q0, q1, q2);
            s_out[3 * mi + 0] = q0;
            s_out[3 * mi + 1] = q1;
            s_out[3 * mi + 2] = q2;
        }
    }
    __syncthreads();

#pragma unroll
    for (int k = 0; k < 6; k++) {
        const int idx = t + k * 256;
        if (idx < nf4) out[fbase + idx] = s_out[idx];
    }
}

extern "C" void kernel_launch(void* const* d_in, const int* in_sizes, int n_in,
                              void* d_out, int out_size)
{
    const float4* in = (const float4*)d_in[0];
    float4* out = (float4*)d_out;
    const int b = in_sizes[0] / 12;  // (B, 3, 4) fp32 -> 12 elements per matrix

    const int full_tiles = b / TILE;        // 8192 for B = 4,194,304
    const int rem = b - full_tiles * TILE;  // 0 here

    if (full_tiles > 0)
        invert_affine_hybrid_kernel<<<full_tiles, 256>>>(in, out);
    if (rem > 0)
        invert_affine_tail_kernel<<<1, 256>>>(in, out, full_tiles * TILE, b);
}